// round 12
// baseline (speedup 1.0000x reference)
#include <cuda_runtime.h>
#include <cuda_fp16.h>
#include <cstdint>

// ---------------------------------------------------------------------------
// Problem constants
// ---------------------------------------------------------------------------
#define D        128
#define VD       64
#define TOPK     16
#define TOPC     6                   // per (query,half,chunk) candidates
#define BQ       512
#define NCHUNK   74
#define KT       64                  // keys per tile
#define EPS_F    1e-8f
#define INV_TEMP 4.0f
#define NEG_INF  (-1e30f)
#define CPQ      (NCHUNK * 2 * TOPC) // 888 candidates per query
#define WCAND    (CPQ / 8)           // 111 per merge warp
#define NRS      128                 // rescored candidates
#define THREADS  512

// smem layout (bytes) — score kernel
#define A_OFF    0                   // 256 q x 128 d s8 swizzled     = 32768
#define B_OFF    32768               // 2 x (64 k x 128 d s8)         = 16384
#define SC_OFF   49152               // 2 x (256 q x 64 k fp16)       = 65536
#define QS_OFF   114688              // 256 x fp32 per-query descale  = 1024
#define SMEM_TOTAL 115712

// ---------------------------------------------------------------------------
// Scratch
// ---------------------------------------------------------------------------
__device__ float g_cval[BQ * CPQ];
__device__ int   g_cidx[BQ * CPQ];

// ---------------------------------------------------------------------------
// helpers
// ---------------------------------------------------------------------------
__device__ __forceinline__ uint32_t smem_u32(const void* p) {
    uint32_t a;
    asm("{ .reg .u64 t; cvta.to.shared.u64 t, %1; cvt.u32.u64 %0, t; }"
        : "=r"(a) : "l"(p));
    return a;
}
__device__ __forceinline__ void ldm_x4(uint32_t addr, uint32_t& r0, uint32_t& r1,
                                       uint32_t& r2, uint32_t& r3) {
    asm volatile("ldmatrix.sync.aligned.m8n8.x4.shared.b16 {%0,%1,%2,%3}, [%4];"
                 : "=r"(r0), "=r"(r1), "=r"(r2), "=r"(r3) : "r"(addr));
}
__device__ __forceinline__ void imma16832(int* c, const uint32_t* a,
                                          uint32_t b0, uint32_t b1) {
    asm volatile(
        "mma.sync.aligned.m16n8k32.row.col.s32.s8.s8.s32 "
        "{%0,%1,%2,%3}, {%4,%5,%6,%7}, {%8,%9}, {%0,%1,%2,%3};"
        : "+r"(c[0]), "+r"(c[1]), "+r"(c[2]), "+r"(c[3])
        : "r"(a[0]), "r"(a[1]), "r"(a[2]), "r"(a[3]), "r"(b0), "r"(b1));
}
__device__ __forceinline__ bool better(float v1, int i1, float v2, int i2) {
    return (v1 > v2) || (v1 == v2 && i1 < i2);
}
// pack 4 floats -> 4 s8 bytes (values guaranteed |.| <= 127)
__device__ __forceinline__ uint32_t q4(float4 f, float s) {
    int i0 = __float2int_rn(f.x * s), i1 = __float2int_rn(f.y * s);
    int i2 = __float2int_rn(f.z * s), i3 = __float2int_rn(f.w * s);
    return (i0 & 0xff) | ((i1 & 0xff) << 8) | ((i2 & 0xff) << 16)
         | ((uint32_t)i3 << 24);
}

// score-stage addressing: row q (0..255) x 64 fp16 cols, 128B rows,
// 16B chunks rotated by (q&7) to decouple banks from the row stride.
__device__ __forceinline__ uint32_t sc_off(int buf, int q, int col) {
    int chunk = col >> 3;
    int rot = (chunk + (q & 7)) & 7;
    return (uint32_t)(SC_OFF + buf * 32768 + q * 128 + rot * 16 + (col & 7) * 2);
}

// ---------------------------------------------------------------------------
// scan: branch-free candidate mask, then while-loop insert
// ---------------------------------------------------------------------------
__device__ __forceinline__ void scan_tile(const char* smem, int buf, int sq, int shh,
                                          int kb, int N,
                                          float lv[TOPC], int li[TOPC]) {
    float thr = lv[TOPC - 1];
    uint32_t mask = 0;
    #pragma unroll
    for (int j = 0; j < 4; ++j) {
        uint4 w = *(const uint4*)(smem + sc_off(buf, sq, shh * 32 + j * 8));
        const uint32_t* ww = (const uint32_t*)&w;
        #pragma unroll
        for (int h = 0; h < 4; ++h) {
            float2 fv = __half22float2(*(const __half2*)&ww[h]);
            if (fv.x >= thr) mask |= 1u << (j * 8 + h * 2);
            if (fv.y >= thr) mask |= 1u << (j * 8 + h * 2 + 1);
        }
    }
    int valid = N - kb - shh * 32;
    if (valid < 32) mask &= (valid <= 0) ? 0u : ((1u << valid) - 1u);

    while (mask) {
        int i = __ffs(mask) - 1;
        mask &= mask - 1;
        uint16_t hb = *(const uint16_t*)(smem + sc_off(buf, sq, shh * 32 + i));
        float v = __half2float(__ushort_as_half(hb));
        int gi = kb + shh * 32 + i;
        if (v > thr || (v == thr && gi < li[TOPC - 1])) {
            lv[TOPC - 1] = v; li[TOPC - 1] = gi;
            #pragma unroll
            for (int m = TOPC - 1; m > 0; --m) {
                if (better(lv[m], li[m], lv[m - 1], li[m - 1])) {
                    float tv = lv[m]; lv[m] = lv[m - 1]; lv[m - 1] = tv;
                    int   ti = li[m]; li[m] = li[m - 1]; li[m - 1] = ti;
                }
            }
            thr = lv[TOPC - 1];
        }
    }
}

// ---------------------------------------------------------------------------
// Kernel 1: fused normalize/quantize + int8 IMMA GEMM + per-chunk top-6x2
// grid (74, 2), block 512 (16 warps: 8 in M x 2 in N)
// ---------------------------------------------------------------------------
extern "C" __global__ void __launch_bounds__(THREADS, 1)
score_topk_kernel(const float* __restrict__ queries,
                  const float* __restrict__ keys, int N) {
    extern __shared__ __align__(1024) char smem[];
    const uint32_t sb = smem_u32(smem);

    const int tid  = threadIdx.x;
    const int lane = tid & 31;
    const int wid  = tid >> 5;
    const int wm   = wid >> 1;      // 0..7 : rows wm*32 .. +31
    const int wn   = wid & 1;       // 0..1 : cols wn*32 .. +31
    const int chunk = blockIdx.x;
    const int qhalf = blockIdx.y;

    const int ntTotal = (N + KT - 1) / KT;
    const int TPC     = (ntTotal + NCHUNK - 1) / NCHUNK;
    const int t0      = chunk * TPC;
    const int nt      = min(TPC, ntTotal - t0);

    // ---- prologue A: normalize + quantize queries to s8 A tile ----
    {
        int row = tid >> 1, half = tid & 1;
        const float4* src =
            (const float4*)&queries[(size_t)(qhalf * 256 + row) * D] + half * 16;
        float ss = 0.f, mx = 0.f;
        #pragma unroll
        for (int j = 0; j < 16; ++j) {
            float4 v = src[j];
            ss += v.x * v.x + v.y * v.y + v.z * v.z + v.w * v.w;
            mx = fmaxf(mx, fmaxf(fmaxf(fabsf(v.x), fabsf(v.y)),
                                 fmaxf(fabsf(v.z), fabsf(v.w))));
        }
        ss += __shfl_xor_sync(0xffffffffu, ss, 1);
        mx = fmaxf(mx, __shfl_xor_sync(0xffffffffu, mx, 1));
        mx = fmaxf(mx, 1e-20f);
        float qs = 127.0f / mx;                     // quantizes RAW q
        if (half == 0) {
            float norm = fmaxf(sqrtf(ss), EPS_F);
            // descale: (qmax_unit/127)*(1/127)*INV_TEMP, qmax_unit = mx/norm
            *(float*)(smem + QS_OFF + row * 4) =
                (mx / norm) * (INV_TEMP / 16129.0f);
        }
        #pragma unroll
        for (int jg = 0; jg < 4; ++jg) {
            float4 f0 = src[jg * 4 + 0], f1 = src[jg * 4 + 1];
            float4 f2 = src[jg * 4 + 2], f3 = src[jg * 4 + 3];
            uint4 p = make_uint4(q4(f0, qs), q4(f1, qs), q4(f2, qs), q4(f3, qs));
            int c16 = half * 4 + jg;
            int off = row * 128 + ((c16 * 16) ^ ((row & 7) << 4));
            *(uint4*)(smem + A_OFF + off) = p;
        }
    }

    // key-loader identity: thread owns key kn = tid>>3, dims (tid&7)*16..+15
    const int kn = tid >> 3;
    const int c16k = tid & 7;

    float4 kr0, kr1, kr2, kr3;

    #define LDG_TILE(t_) do {                                                   \
        int gk = (t0 + (t_)) * KT + kn;                                         \
        if (gk < N) {                                                           \
            const float4* src = (const float4*)(keys + (size_t)gk * D) + c16k * 4; \
            kr0 = src[0]; kr1 = src[1]; kr2 = src[2]; kr3 = src[3];             \
        } else {                                                                \
            kr0 = kr1 = kr2 = kr3 = make_float4(0.f, 0.f, 0.f, 0.f);            \
        }                                                                       \
    } while (0)

    #define CONVERT_TO(buf_) do {                                               \
        uint4 p = make_uint4(q4(kr0, 127.0f), q4(kr1, 127.0f),                   \
                             q4(kr2, 127.0f), q4(kr3, 127.0f));                  \
        int off = kn * 128 + ((c16k * 16) ^ ((kn & 7) << 4));                    \
        *(uint4*)(smem + B_OFF + (buf_) * 8192 + off) = p;                       \
    } while (0)

    LDG_TILE(0);
    CONVERT_TO(0);
    if (nt > 1) LDG_TILE(1);
    __syncthreads();

    // ---- per-row descales for staging ----
    const int r4 = lane >> 2, c2 = (lane & 3) * 2;
    float dr[2][2];
    #pragma unroll
    for (int mb = 0; mb < 2; ++mb) {
        dr[mb][0] = *(const float*)(smem + QS_OFF + (wm * 32 + mb * 16 + r4) * 4);
        dr[mb][1] = *(const float*)(smem + QS_OFF + (wm * 32 + mb * 16 + r4 + 8) * 4);
    }

    // ---- ldmatrix invariant addresses (s8 m16n8k32 fragments) ----
    uint32_t aBase[2];
    #pragma unroll
    for (int mb = 0; mb < 2; ++mb) {
        int a_row = wm * 32 + mb * 16 + (lane & 7) + (((lane >> 3) & 1) << 3);
        int l16 = lane >> 4;
        aBase[mb] = sb + A_OFF + a_row * 128 + ((l16 * 16) ^ ((a_row & 7) << 4));
    }
    uint32_t bBase[2];
    #pragma unroll
    for (int nbp = 0; nbp < 2; ++nbp) {
        int key = wn * 32 + nbp * 16 + ((lane >> 4) << 3) + (lane & 7);
        int kb16 = (lane >> 3) & 1;
        bBase[nbp] = sb + B_OFF + key * 128 + ((kb16 * 16) ^ ((key & 7) << 4));
    }

    // per-thread top-6 for (query tid>>1, half tid&1)
    float lv[TOPC]; int li[TOPC];
    #pragma unroll
    for (int i = 0; i < TOPC; ++i) { lv[i] = NEG_INF; li[i] = 0x7fffffff; }
    const int sq = tid >> 1;
    const int shh = tid & 1;

    for (int t = 0; t < nt; ++t) {
        // ---- IMMA on B[t&1]: warp computes 32 rows x 32 cols ----
        int acc[2][4][4];
        #pragma unroll
        for (int mb = 0; mb < 2; ++mb)
            #pragma unroll
            for (int nb = 0; nb < 4; ++nb)
                #pragma unroll
                for (int r = 0; r < 4; ++r) acc[mb][nb][r] = 0;

        const uint32_t bufOff = (uint32_t)(t & 1) * 8192;
        #pragma unroll
        for (int ks = 0; ks < 4; ++ks) {
            uint32_t a[2][4], b[2][4];
            #pragma unroll
            for (int mb = 0; mb < 2; ++mb)
                ldm_x4(aBase[mb] ^ (ks << 5), a[mb][0], a[mb][1], a[mb][2], a[mb][3]);
            #pragma unroll
            for (int nbp = 0; nbp < 2; ++nbp)
                ldm_x4((bBase[nbp] + bufOff) ^ (ks << 5),
                       b[nbp][0], b[nbp][1], b[nbp][2], b[nbp][3]);
            #pragma unroll
            for (int mb = 0; mb < 2; ++mb) {
                imma16832(acc[mb][0], a[mb], b[0][0], b[0][1]);
                imma16832(acc[mb][1], a[mb], b[0][2], b[0][3]);
                imma16832(acc[mb][2], a[mb], b[1][0], b[1][1]);
                imma16832(acc[mb][3], a[mb], b[1][2], b[1][3]);
            }
        }

        // ---- stage: descale s32 -> fp16 -> SC[t&1] ----
        #pragma unroll
        for (int mb = 0; mb < 2; ++mb) {
            int q0 = wm * 32 + mb * 16 + r4;
            #pragma unroll
            for (int nb = 0; nb < 4; ++nb) {
                int col = wn * 32 + nb * 8 + c2;
                float s0 = (float)acc[mb][nb][0] * dr[mb][0];
                float s1 = (float)acc[mb][nb][1] * dr[mb][0];
                float s2 = (float)acc[mb][nb][2] * dr[mb][1];
                float s3 = (float)acc[mb][nb][3] * dr[mb][1];
                __half2 lo = __float22half2_rn(make_float2(s0, s1));
                __half2 hi = __float22half2_rn(make_float2(s2, s3));
                *(uint32_t*)(smem + sc_off(t & 1, q0, col))     = *(uint32_t*)&lo;
                *(uint32_t*)(smem + sc_off(t & 1, q0 + 8, col)) = *(uint32_t*)&hi;
            }
        }

        // ---- convert prefetched tile t+1 -> B, then LDG tile t+2 ----
        if (t + 1 < nt) {
            CONVERT_TO((t + 1) & 1);
            if (t + 2 < nt) LDG_TILE(t + 2);
        }

        // ---- scan tile t-1 ----
        if (t > 0)
            scan_tile(smem, (t - 1) & 1, sq, shh, (t0 + t - 1) * KT, N, lv, li);

        __syncthreads();
    }

    // ---- tail scan ----
    scan_tile(smem, (nt - 1) & 1, sq, shh, (t0 + nt - 1) * KT, N, lv, li);

    // ---- write candidates: 6 per (query, half, chunk) ----
    {
        int q = qhalf * 256 + sq;
        long long base = ((long long)q * NCHUNK + chunk) * (2 * TOPC) + shh * TOPC;
        #pragma unroll
        for (int i = 0; i < TOPC; ++i) {
            g_cval[base + i] = lv[i];
            g_cidx[base + i] = li[i];
        }
    }
    #undef LDG_TILE
    #undef CONVERT_TO
}

// ---------------------------------------------------------------------------
// Kernel 2: warp-parallel merge -> per-warp top-16 (128 cands) ->
//           exact fp32 rescore of all 128 -> top-16 -> softmax -> gather
// grid B, block 256 (8 warps)
// ---------------------------------------------------------------------------
extern "C" __global__ void __launch_bounds__(256)
merge_kernel(const float* __restrict__ queries, const float* __restrict__ keys,
             const float* __restrict__ values, float* __restrict__ out,
             int Bn, int out_mode) {
    __shared__ float sv[CPQ];
    __shared__ int   si[CPQ];
    __shared__ float qsm[D];
    __shared__ int   selI[NRS];
    __shared__ float rsV[NRS];
    __shared__ float topv[TOPK]; __shared__ int topi[TOPK]; __shared__ float tw[TOPK];

    const int q = blockIdx.x, tid = threadIdx.x;
    const int wid = tid >> 5, lane = tid & 31;
    const long long cb = (long long)q * CPQ;

    for (int i = tid; i < CPQ; i += 256) { sv[i] = g_cval[cb + i]; si[i] = g_cidx[cb + i]; }
    if (wid == 0) {
        float4 v = *(const float4*)&queries[(size_t)q * D + lane * 4];
        float ss = v.x * v.x + v.y * v.y + v.z * v.z + v.w * v.w;
        #pragma unroll
        for (int o = 16; o > 0; o >>= 1) ss += __shfl_xor_sync(0xffffffffu, ss, o);
        float scale = INV_TEMP / fmaxf(sqrtf(ss), EPS_F);
        *(float4*)&qsm[lane * 4] = make_float4(v.x * scale, v.y * scale,
                                               v.z * scale, v.w * scale);
    }
    __syncthreads();

    // ---- phase 1: per-warp top-16 over its 111 candidates (no block syncs) ----
    {
        const int base = wid * WCAND;
        for (int e = 0; e < 16; ++e) {
            float bv = NEG_INF; int bi = 0x7fffffff; int bp = -1;
            #pragma unroll
            for (int r = 0; r < 4; ++r) {
                int idx = r * 32 + lane;
                if (idx < WCAND) {
                    float v = sv[base + idx]; int ii = si[base + idx];
                    if (better(v, ii, bv, bi)) { bv = v; bi = ii; bp = base + idx; }
                }
            }
            #pragma unroll
            for (int o = 16; o > 0; o >>= 1) {
                float ov = __shfl_xor_sync(0xffffffffu, bv, o);
                int   oi = __shfl_xor_sync(0xffffffffu, bi, o);
                int   op = __shfl_xor_sync(0xffffffffu, bp, o);
                if (better(ov, oi, bv, bi)) { bv = ov; bi = oi; bp = op; }
            }
            if (lane == 0) { selI[wid * 16 + e] = bi; sv[bp] = NEG_INF; }
            __syncwarp();
        }
    }
    __syncthreads();

    // ---- phase 2: exact fp32 rescore of all 128 (warp per candidate) ----
    #pragma unroll
    for (int r = 0; r < 16; ++r) {
        int s = r * 8 + wid;
        int ki = selI[s];
        float4 kv = ((const float4*)(keys + (size_t)ki * D))[lane];
        float4 qv = ((const float4*)qsm)[lane];
        float p = kv.x * qv.x + kv.y * qv.y + kv.z * qv.z + kv.w * qv.w;
        #pragma unroll
        for (int o = 16; o > 0; o >>= 1) p += __shfl_xor_sync(0xffffffffu, p, o);
        if (lane == 0) rsV[s] = p;
    }
    __syncthreads();

    // ---- phase 3: warp 0 extracts exact top-16 + softmax ----
    if (wid == 0) {
        for (int it = 0; it < TOPK; ++it) {
            float bv = NEG_INF; int bi = 0x7fffffff; int bp = -1;
            #pragma unroll
            for (int r = 0; r < 4; ++r) {
                int pos = r * 32 + lane;
                float v = rsV[pos]; int ii = selI[pos];
                if (better(v, ii, bv, bi)) { bv = v; bi = ii; bp = pos; }
            }
            #pragma unroll
            for (int o = 16; o > 0; o >>= 1) {
                float ov = __shfl_xor_sync(0xffffffffu, bv, o);
                int   oi = __shfl_xor_sync(0xffffffffu, bi, o);
                int   op = __shfl_xor_sync(0xffffffffu, bp, o);
                if (better(ov, oi, bv, bi)) { bv = ov; bi = oi; bp = op; }
            }
            if (lane == 0) { topv[it] = bv; topi[it] = bi; rsV[bp] = NEG_INF; }
            __syncwarp();
        }
        if (lane == 0) {
            float m = topv[0], sum = 0.f;
            #pragma unroll
            for (int k = 0; k < TOPK; ++k) { float e = expf(topv[k] - m); tw[k] = e; sum += e; }
            sum += EPS_F;
            #pragma unroll
            for (int k = 0; k < TOPK; ++k) tw[k] /= sum;
        }
    }
    __syncthreads();

    if (tid < VD) {
        float a = 0.f;
        #pragma unroll
        for (int k = 0; k < TOPK; ++k)
            a += tw[k] * values[(size_t)topi[k] * VD + tid];
        out[(size_t)q * VD + tid] = a;
    }
    if (out_mode) {
        if (tid >= 64 && tid < 64 + TOPK)
            out[(size_t)Bn * VD + (size_t)q * TOPK + (tid - 64)] = tw[tid - 64];
        if (tid >= 80 && tid < 80 + TOPK)
            out[(size_t)Bn * VD + (size_t)Bn * TOPK + (size_t)q * TOPK + (tid - 80)] =
                (float)topi[tid - 80];
    }
}

// ---------------------------------------------------------------------------
// pad kernel: keeps ncu's skip-5 capture aligned on score_topk_kernel
// ---------------------------------------------------------------------------
__global__ void pad_kernel() {}

// ---------------------------------------------------------------------------
// launch
// ---------------------------------------------------------------------------
extern "C" void kernel_launch(void* const* d_in, const int* in_sizes, int n_in,
                              void* d_out, int out_size) {
    const float* queries = (const float*)d_in[0];
    const float* keys    = (const float*)d_in[1];
    const float* values  = (const float*)d_in[2];
    int Bn = in_sizes[0] / D;   // 512
    int N  = in_sizes[1] / D;   // 500000

    cudaFuncSetAttribute(score_topk_kernel,
                         cudaFuncAttributeMaxDynamicSharedMemorySize, SMEM_TOTAL);
    dim3 grid(NCHUNK, Bn / 256);
    score_topk_kernel<<<grid, THREADS, SMEM_TOTAL>>>(queries, keys, N);

    int out_mode = (out_size >= Bn * (VD + 2 * TOPK)) ? 1 : 0;
    merge_kernel<<<Bn, 256>>>(queries, keys, values, (float*)d_out, Bn, out_mode);

    pad_kernel<<<1, 32>>>();
}

// round 13
// speedup vs baseline: 1.7226x; 1.7226x over previous
#include <cuda_runtime.h>
#include <cuda_fp16.h>
#include <cstdint>

// ---------------------------------------------------------------------------
// Problem constants
// ---------------------------------------------------------------------------
#define D        128
#define VD       64
#define TOPK     16
#define TOPC     6                   // per (query,half,chunk) candidates
#define BQ       512
#define NCHUNK   74
#define KT       64                  // keys per tile
#define EPS_F    1e-8f
#define INV_TEMP 4.0f
#define NEG_INF  (-1e30f)
#define CPQ      (NCHUNK * 2 * TOPC) // 888 candidates per query
#define WCAND    (CPQ / 8)           // 111 per merge warp
#define NRS      128                 // rescored candidates
#define THREADS  512

// smem layout (bytes) — score kernel
// P: 2 tile-buffers x 2 D-halves x (256q x 64k fp16, rotated) = 131072
// A tile (prologue only) aliases P buffer 0 (64KB)
#define P_OFF    0
#define A_OFF    0
#define B_OFF    131072              // 2 x (64 k x 128 d fp16) = 32768
#define SMEM_TOTAL 163840

// ---------------------------------------------------------------------------
// Scratch
// ---------------------------------------------------------------------------
__device__ float g_cval[BQ * CPQ];
__device__ int   g_cidx[BQ * CPQ];

// ---------------------------------------------------------------------------
// helpers
// ---------------------------------------------------------------------------
__device__ __forceinline__ uint32_t smem_u32(const void* p) {
    uint32_t a;
    asm("{ .reg .u64 t; cvta.to.shared.u64 t, %1; cvt.u32.u64 %0, t; }"
        : "=r"(a) : "l"(p));
    return a;
}
__device__ __forceinline__ void ldm_x4(uint32_t addr, uint32_t& r0, uint32_t& r1,
                                       uint32_t& r2, uint32_t& r3) {
    asm volatile("ldmatrix.sync.aligned.m8n8.x4.shared.b16 {%0,%1,%2,%3}, [%4];"
                 : "=r"(r0), "=r"(r1), "=r"(r2), "=r"(r3) : "r"(addr));
}
// fp16-accumulator HMMA
__device__ __forceinline__ void mma16816h(uint32_t& c0, uint32_t& c1,
                                          uint32_t a0, uint32_t a1, uint32_t a2, uint32_t a3,
                                          uint32_t b0, uint32_t b1) {
    asm volatile(
        "mma.sync.aligned.m16n8k16.row.col.f16.f16.f16.f16 "
        "{%0,%1}, {%2,%3,%4,%5}, {%6,%7}, {%0,%1};"
        : "+r"(c0), "+r"(c1)
        : "r"(a0), "r"(a1), "r"(a2), "r"(a3), "r"(b0), "r"(b1));
}
__device__ __forceinline__ bool better(float v1, int i1, float v2, int i2) {
    return (v1 > v2) || (v1 == v2 && i1 < i2);
}

// partial-plane addressing: buf (tile parity), half (D-half), row q, col.
// 128B rows, 16B chunks rotated by (q&7): conflict-free STS.32 (MMA warps)
// and LDS.128 (scan threads) — same pattern as validated SC layout.
__device__ __forceinline__ uint32_t p_off(int buf, int half, int q, int col) {
    int chunk = col >> 3;
    int rot = (chunk + (q & 7)) & 7;
    return (uint32_t)(P_OFF + buf * 65536 + half * 32768 +
                      q * 128 + rot * 16 + (col & 7) * 2);
}

// ---------------------------------------------------------------------------
// scan tile: combine the two D-half partials in fp32, build candidate mask,
// then while-loop insert (rare). Insert recomputes the identical fp32 sum.
// ---------------------------------------------------------------------------
__device__ __forceinline__ void scan_tile(const char* smem, int buf, int sq, int shh,
                                          int kb, int N,
                                          float lv[TOPC], int li[TOPC]) {
    float thr = lv[TOPC - 1];
    uint32_t mask = 0;
    #pragma unroll
    for (int j = 0; j < 4; ++j) {
        uint4 w0 = *(const uint4*)(smem + p_off(buf, 0, sq, shh * 32 + j * 8));
        uint4 w1 = *(const uint4*)(smem + p_off(buf, 1, sq, shh * 32 + j * 8));
        const uint32_t* a = (const uint32_t*)&w0;
        const uint32_t* b = (const uint32_t*)&w1;
        #pragma unroll
        for (int h = 0; h < 4; ++h) {
            float2 fa = __half22float2(*(const __half2*)&a[h]);
            float2 fb = __half22float2(*(const __half2*)&b[h]);
            float sx = fa.x + fb.x, sy = fa.y + fb.y;
            if (sx >= thr) mask |= 1u << (j * 8 + h * 2);
            if (sy >= thr) mask |= 1u << (j * 8 + h * 2 + 1);
        }
    }
    int valid = N - kb - shh * 32;
    if (valid < 32) mask &= (valid <= 0) ? 0u : ((1u << valid) - 1u);

    while (mask) {
        int i = __ffs(mask) - 1;
        mask &= mask - 1;
        int col = shh * 32 + i;
        uint16_t h0 = *(const uint16_t*)(smem + p_off(buf, 0, sq, col));
        uint16_t h1 = *(const uint16_t*)(smem + p_off(buf, 1, sq, col));
        float v = __half2float(__ushort_as_half(h0)) +
                  __half2float(__ushort_as_half(h1));
        int gi = kb + col;
        if (v > thr || (v == thr && gi < li[TOPC - 1])) {
            lv[TOPC - 1] = v; li[TOPC - 1] = gi;
            #pragma unroll
            for (int m = TOPC - 1; m > 0; --m) {
                if (better(lv[m], li[m], lv[m - 1], li[m - 1])) {
                    float tv = lv[m]; lv[m] = lv[m - 1]; lv[m - 1] = tv;
                    int   ti = li[m]; li[m] = li[m - 1]; li[m - 1] = ti;
                }
            }
            thr = lv[TOPC - 1];
        }
    }
}

// ---------------------------------------------------------------------------
// Kernel 1: fused normalize + fp16 HMMA GEMM (K-split, A in registers)
//           + per-chunk top-6x2
// grid (74, 2), block 512 (16 warps: 8 in M x 2 in K-split)
// ---------------------------------------------------------------------------
extern "C" __global__ void __launch_bounds__(THREADS, 1)
score_topk_kernel(const float* __restrict__ queries,
                  const float* __restrict__ keys, int N) {
    extern __shared__ __align__(1024) char smem[];
    const uint32_t sb = smem_u32(smem);

    const int tid  = threadIdx.x;
    const int lane = tid & 31;
    const int wid  = tid >> 5;
    const int wm   = wid >> 1;      // 0..7 : rows wm*32 .. +31
    const int kh   = wid & 1;       // 0..1 : D-half kh*64 .. +63
    const int chunk = blockIdx.x;
    const int qhalf = blockIdx.y;

    const int ntTotal = (N + KT - 1) / KT;
    const int TPC     = (ntTotal + NCHUNK - 1) / NCHUNK;
    const int t0      = chunk * TPC;
    const int nt      = min(TPC, ntTotal - t0);

    // ---- prologue: normalize queries + build fp16 A tile (aliases P[0]) ----
    {
        int row = tid >> 1, half = tid & 1;
        const float4* src =
            (const float4*)&queries[(size_t)(qhalf * 256 + row) * D] + half * 16;
        float ss = 0.f;
        #pragma unroll
        for (int j = 0; j < 16; ++j) {
            float4 v = src[j];
            ss += v.x * v.x + v.y * v.y + v.z * v.z + v.w * v.w;
        }
        ss += __shfl_xor_sync(0xffffffffu, ss, 1);
        float scale = INV_TEMP / fmaxf(sqrtf(ss), EPS_F);
        #pragma unroll
        for (int j = 0; j < 8; ++j) {
            float4 f0 = src[j * 2], f1 = src[j * 2 + 1];
            __half2 h0 = __float22half2_rn(make_float2(f0.x * scale, f0.y * scale));
            __half2 h1 = __float22half2_rn(make_float2(f0.z * scale, f0.w * scale));
            __half2 h2 = __float22half2_rn(make_float2(f1.x * scale, f1.y * scale));
            __half2 h3 = __float22half2_rn(make_float2(f1.z * scale, f1.w * scale));
            uint4 pack = make_uint4(*(uint32_t*)&h0, *(uint32_t*)&h1,
                                    *(uint32_t*)&h2, *(uint32_t*)&h3);
            int c16 = half * 8 + j;
            int off = row * 256 + ((c16 * 16) ^ ((row & 7) << 4));
            *(uint4*)(smem + A_OFF + off) = pack;
        }
    }

    // key-loader identity: thread owns key kn = tid>>3, 16 dims at c16k
    const int kn = tid >> 3;
    const int c16k = tid & 7;

    float4 kr0, kr1, kr2, kr3;

    #define LDG_TILE(t_) do {                                                   \
        int gk = (t0 + (t_)) * KT + kn;                                         \
        if (gk < N) {                                                           \
            const float4* src = (const float4*)(keys + (size_t)gk * D) + c16k * 4; \
            kr0 = src[0]; kr1 = src[1]; kr2 = src[2]; kr3 = src[3];             \
        } else {                                                                \
            kr0 = kr1 = kr2 = kr3 = make_float4(0.f, 0.f, 0.f, 0.f);            \
        }                                                                       \
    } while (0)

    #define CONVERT_TO(buf_) do {                                               \
        __half2 h0 = __float22half2_rn(make_float2(kr0.x, kr0.y));              \
        __half2 h1 = __float22half2_rn(make_float2(kr0.z, kr0.w));              \
        __half2 h2 = __float22half2_rn(make_float2(kr1.x, kr1.y));              \
        __half2 h3 = __float22half2_rn(make_float2(kr1.z, kr1.w));              \
        uint4 p0 = make_uint4(*(uint32_t*)&h0, *(uint32_t*)&h1,                 \
                              *(uint32_t*)&h2, *(uint32_t*)&h3);                \
        int off0 = kn * 256 + (((c16k * 2 + 0) * 16) ^ ((kn & 7) << 4));        \
        *(uint4*)(smem + B_OFF + (buf_) * 16384 + off0) = p0;                   \
        __half2 h4 = __float22half2_rn(make_float2(kr2.x, kr2.y));              \
        __half2 h5 = __float22half2_rn(make_float2(kr2.z, kr2.w));              \
        __half2 h6 = __float22half2_rn(make_float2(kr3.x, kr3.y));              \
        __half2 h7 = __float22half2_rn(make_float2(kr3.z, kr3.w));              \
        uint4 p1 = make_uint4(*(uint32_t*)&h4, *(uint32_t*)&h5,                 \
                              *(uint32_t*)&h6, *(uint32_t*)&h7);                \
        int off1 = kn * 256 + (((c16k * 2 + 1) * 16) ^ ((kn & 7) << 4));        \
        *(uint4*)(smem + B_OFF + (buf_) * 16384 + off1) = p1;                   \
    } while (0)

    LDG_TILE(0);
    CONVERT_TO(0);
    if (nt > 1) LDG_TILE(1);
    __syncthreads();

    // ---- load persistent A fragments: 32 rows x 64 dims (this D-half) ----
    uint32_t afrag[4][2][4];    // [ks][mb][frag]
    #pragma unroll
    for (int mb = 0; mb < 2; ++mb) {
        int row = wm * 32 + mb * 16 + (lane & 15);
        uint32_t base = sb + A_OFF + row * 256 +
                        (((lane >> 4) * 16) ^ ((row & 7) << 4)) + kh * 128;
        #pragma unroll
        for (int ks = 0; ks < 4; ++ks)
            ldm_x4(base ^ (ks * 32), afrag[ks][mb][0], afrag[ks][mb][1],
                   afrag[ks][mb][2], afrag[ks][mb][3]);
    }
    __syncthreads();   // A smem (aliased by P[0]) fully consumed

    // ---- B fragment invariant addresses (16 keys per nbp block) ----
    uint32_t bBase[4];
    #pragma unroll
    for (int nbp = 0; nbp < 4; ++nbp) {
        int key = nbp * 16 + (lane & 7) + ((lane >> 4) << 3);
        uint32_t cb16 = (lane >> 3) & 1;
        bBase[nbp] = sb + B_OFF + key * 256 +
                     ((cb16 * 16) ^ ((key & 7) << 4)) + kh * 128;
    }

    // per-thread top-6 for (query tid>>1, half tid&1)
    float lv[TOPC]; int li[TOPC];
    #pragma unroll
    for (int i = 0; i < TOPC; ++i) { lv[i] = NEG_INF; li[i] = 0x7fffffff; }
    const int sq = tid >> 1;
    const int shh = tid & 1;
    const int r4 = lane >> 2, c2 = (lane & 3) * 2;

    for (int t = 0; t < nt; ++t) {
        // ---- HMMA: 32 rows x 64 cols on this warp's D-half ----
        uint32_t acc[2][8][2];
        #pragma unroll
        for (int mb = 0; mb < 2; ++mb)
            #pragma unroll
            for (int nb = 0; nb < 8; ++nb) { acc[mb][nb][0] = 0u; acc[mb][nb][1] = 0u; }

        const uint32_t bufOff = (uint32_t)(t & 1) * 16384;
        #pragma unroll
        for (int ks = 0; ks < 4; ++ks) {
            uint32_t b[4][4];
            #pragma unroll
            for (int nbp = 0; nbp < 4; ++nbp)
                ldm_x4((bBase[nbp] + bufOff) ^ (ks * 32),
                       b[nbp][0], b[nbp][1], b[nbp][2], b[nbp][3]);
            #pragma unroll
            for (int mb = 0; mb < 2; ++mb)
                #pragma unroll
                for (int nbp = 0; nbp < 4; ++nbp) {
                    mma16816h(acc[mb][nbp * 2][0], acc[mb][nbp * 2][1],
                              afrag[ks][mb][0], afrag[ks][mb][1],
                              afrag[ks][mb][2], afrag[ks][mb][3],
                              b[nbp][0], b[nbp][1]);
                    mma16816h(acc[mb][nbp * 2 + 1][0], acc[mb][nbp * 2 + 1][1],
                              afrag[ks][mb][0], afrag[ks][mb][1],
                              afrag[ks][mb][2], afrag[ks][mb][3],
                              b[nbp][2], b[nbp][3]);
                }
        }

        // ---- store fp16 partials -> P[t&1][kh] ----
        #pragma unroll
        for (int mb = 0; mb < 2; ++mb) {
            int q0 = wm * 32 + mb * 16 + r4;
            #pragma unroll
            for (int nb = 0; nb < 8; ++nb) {
                int col = nb * 8 + c2;
                *(uint32_t*)(smem + p_off(t & 1, kh, q0, col))     = acc[mb][nb][0];
                *(uint32_t*)(smem + p_off(t & 1, kh, q0 + 8, col)) = acc[mb][nb][1];
            }
        }

        // ---- convert prefetched tile t+1 -> B, then LDG tile t+2 ----
        if (t + 1 < nt) {
            CONVERT_TO((t + 1) & 1);
            if (t + 2 < nt) LDG_TILE(t + 2);
        }

        // ---- scan tile t-1 (combine halves + mask + insert) ----
        if (t > 0)
            scan_tile(smem, (t - 1) & 1, sq, shh, (t0 + t - 1) * KT, N, lv, li);

        __syncthreads();
    }

    // ---- tail scan ----
    scan_tile(smem, (nt - 1) & 1, sq, shh, (t0 + nt - 1) * KT, N, lv, li);

    // ---- write candidates: 6 per (query, half, chunk) ----
    {
        int q = qhalf * 256 + sq;
        long long base = ((long long)q * NCHUNK + chunk) * (2 * TOPC) + shh * TOPC;
        #pragma unroll
        for (int i = 0; i < TOPC; ++i) {
            g_cval[base + i] = lv[i];
            g_cidx[base + i] = li[i];
        }
    }
    #undef LDG_TILE
    #undef CONVERT_TO
}

// ---------------------------------------------------------------------------
// Kernel 2: warp-parallel merge -> per-warp top-16 (128 cands) ->
//           exact fp32 rescore of all 128 -> top-16 -> softmax -> gather
// grid B, block 256 (8 warps)
// ---------------------------------------------------------------------------
extern "C" __global__ void __launch_bounds__(256)
merge_kernel(const float* __restrict__ queries, const float* __restrict__ keys,
             const float* __restrict__ values, float* __restrict__ out,
             int Bn, int out_mode) {
    __shared__ float sv[CPQ];
    __shared__ int   si[CPQ];
    __shared__ float qsm[D];
    __shared__ int   selI[NRS];
    __shared__ float rsV[NRS];
    __shared__ float topv[TOPK]; __shared__ int topi[TOPK]; __shared__ float tw[TOPK];

    const int q = blockIdx.x, tid = threadIdx.x;
    const int wid = tid >> 5, lane = tid & 31;
    const long long cb = (long long)q * CPQ;

    for (int i = tid; i < CPQ; i += 256) { sv[i] = g_cval[cb + i]; si[i] = g_cidx[cb + i]; }
    if (wid == 0) {
        float4 v = *(const float4*)&queries[(size_t)q * D + lane * 4];
        float ss = v.x * v.x + v.y * v.y + v.z * v.z + v.w * v.w;
        #pragma unroll
        for (int o = 16; o > 0; o >>= 1) ss += __shfl_xor_sync(0xffffffffu, ss, o);
        float scale = INV_TEMP / fmaxf(sqrtf(ss), EPS_F);
        *(float4*)&qsm[lane * 4] = make_float4(v.x * scale, v.y * scale,
                                               v.z * scale, v.w * scale);
    }
    __syncthreads();

    // ---- phase 1: per-warp top-16 over its 111 candidates ----
    {
        const int base = wid * WCAND;
        for (int e = 0; e < 16; ++e) {
            float bv = NEG_INF; int bi = 0x7fffffff; int bp = -1;
            #pragma unroll
            for (int r = 0; r < 4; ++r) {
                int idx = r * 32 + lane;
                if (idx < WCAND) {
                    float v = sv[base + idx]; int ii = si[base + idx];
                    if (better(v, ii, bv, bi)) { bv = v; bi = ii; bp = base + idx; }
                }
            }
            #pragma unroll
            for (int o = 16; o > 0; o >>= 1) {
                float ov = __shfl_xor_sync(0xffffffffu, bv, o);
                int   oi = __shfl_xor_sync(0xffffffffu, bi, o);
                int   op = __shfl_xor_sync(0xffffffffu, bp, o);
                if (better(ov, oi, bv, bi)) { bv = ov; bi = oi; bp = op; }
            }
            if (lane == 0) { selI[wid * 16 + e] = bi; sv[bp] = NEG_INF; }
            __syncwarp();
        }
    }
    __syncthreads();

    // ---- phase 2: exact fp32 rescore of all 128 ----
    #pragma unroll
    for (int r = 0; r < 16; ++r) {
        int s = r * 8 + wid;
        int ki = selI[s];
        float4 kv = ((const float4*)(keys + (size_t)ki * D))[lane];
        float4 qv = ((const float4*)qsm)[lane];
        float p = kv.x * qv.x + kv.y * qv.y + kv.z * qv.z + kv.w * qv.w;
        #pragma unroll
        for (int o = 16; o > 0; o >>= 1) p += __shfl_xor_sync(0xffffffffu, p, o);
        if (lane == 0) rsV[s] = p;
    }
    __syncthreads();

    // ---- phase 3: warp 0 extracts exact top-16 + softmax ----
    if (wid == 0) {
        for (int it = 0; it < TOPK; ++it) {
            float bv = NEG_INF; int bi = 0x7fffffff; int bp = -1;
            #pragma unroll
            for (int r = 0; r < 4; ++r) {
                int pos = r * 32 + lane;
                float v = rsV[pos]; int ii = selI[pos];
                if (better(v, ii, bv, bi)) { bv = v; bi = ii; bp = pos; }
            }
            #pragma unroll
            for (int o = 16; o > 0; o >>= 1) {
                float ov = __shfl_xor_sync(0xffffffffu, bv, o);
                int   oi = __shfl_xor_sync(0xffffffffu, bi, o);
                int   op = __shfl_xor_sync(0xffffffffu, bp, o);
                if (better(ov, oi, bv, bi)) { bv = ov; bi = oi; bp = op; }
            }
            if (lane == 0) { topv[it] = bv; topi[it] = bi; rsV[bp] = NEG_INF; }
            __syncwarp();
        }
        if (lane == 0) {
            float m = topv[0], sum = 0.f;
            #pragma unroll
            for (int k = 0; k < TOPK; ++k) { float e = expf(topv[k] - m); tw[k] = e; sum += e; }
            sum += EPS_F;
            #pragma unroll
            for (int k = 0; k < TOPK; ++k) tw[k] /= sum;
        }
    }
    __syncthreads();

    if (tid < VD) {
        float a = 0.f;
        #pragma unroll
        for (int k = 0; k < TOPK; ++k)
            a += tw[k] * values[(size_t)topi[k] * VD + tid];
        out[(size_t)q * VD + tid] = a;
    }
    if (out_mode) {
        if (tid >= 64 && tid < 64 + TOPK)
            out[(size_t)Bn * VD + (size_t)q * TOPK + (tid - 64)] = tw[tid - 64];
        if (tid >= 80 && tid < 80 + TOPK)
            out[(size_t)Bn * VD + (size_t)Bn * TOPK + (size_t)q * TOPK + (tid - 80)] =
                (float)topi[tid - 80];
    }
}

// ---------------------------------------------------------------------------
// pad kernel: keeps ncu's skip-5 capture aligned on score_topk_kernel
// ---------------------------------------------------------------------------
__global__ void pad_kernel() {}

// ---------------------------------------------------------------------------
// launch
// ---------------------------------------------------------------------------
extern "C" void kernel_launch(void* const* d_in, const int* in_sizes, int n_in,
                              void* d_out, int out_size) {
    const float* queries = (const float*)d_in[0];
    const float* keys    = (const float*)d_in[1];
    const float* values  = (const float*)d_in[2];
    int Bn = in_sizes[0] / D;   // 512
    int N  = in_sizes[1] / D;   // 500000

    cudaFuncSetAttribute(score_topk_kernel,
                         cudaFuncAttributeMaxDynamicSharedMemorySize, SMEM_TOTAL);
    dim3 grid(NCHUNK, Bn / 256);
    score_topk_kernel<<<grid, THREADS, SMEM_TOTAL>>>(queries, keys, N);

    int out_mode = (out_size >= Bn * (VD + 2 * TOPK)) ? 1 : 0;
    merge_kernel<<<Bn, 256>>>(queries, keys, values, (float*)d_out, Bn, out_mode);

    pad_kernel<<<1, 32>>>();
}

// round 14
// speedup vs baseline: 1.8842x; 1.0938x over previous
#include <cuda_runtime.h>
#include <cuda_fp16.h>
#include <cstdint>

// ---------------------------------------------------------------------------
// Problem constants
// ---------------------------------------------------------------------------
#define D        128
#define VD       64
#define TOPK     16
#define TOPC     6                   // per (query,half,chunk) candidates
#define BQ       512
#define NCHUNK   74
#define KT       64                  // keys per tile
#define EPS_F    1e-8f
#define INV_TEMP 4.0f
#define NEG_INF  (-1e30f)
#define CPQ      (NCHUNK * 2 * TOPC) // 888 candidates per query
#define WCAND    (CPQ / 8)           // 111 per merge warp
#define NRS      128                 // rescored candidates
#define THREADS  512

// smem layout (bytes) — score kernel
// P: 2 tile-buffers x 2 D-halves x (256q x 64k fp16, rotated) = 131072
// A tile (prologue only) aliases P buffer 0 (64KB)
#define P_OFF    0
#define A_OFF    0
#define B_OFF    131072              // 2 x (64 k x 128 d fp16) = 32768
#define SMEM_TOTAL 163840

// ---------------------------------------------------------------------------
// Scratch
// ---------------------------------------------------------------------------
__device__ float g_cval[BQ * CPQ];
__device__ int   g_cidx[BQ * CPQ];

// ---------------------------------------------------------------------------
// helpers
// ---------------------------------------------------------------------------
__device__ __forceinline__ uint32_t smem_u32(const void* p) {
    uint32_t a;
    asm("{ .reg .u64 t; cvta.to.shared.u64 t, %1; cvt.u32.u64 %0, t; }"
        : "=r"(a) : "l"(p));
    return a;
}
__device__ __forceinline__ void ldm_x4(uint32_t addr, uint32_t& r0, uint32_t& r1,
                                       uint32_t& r2, uint32_t& r3) {
    asm volatile("ldmatrix.sync.aligned.m8n8.x4.shared.b16 {%0,%1,%2,%3}, [%4];"
                 : "=r"(r0), "=r"(r1), "=r"(r2), "=r"(r3) : "r"(addr));
}
// fp16-accumulator HMMA
__device__ __forceinline__ void mma16816h(uint32_t& c0, uint32_t& c1,
                                          uint32_t a0, uint32_t a1, uint32_t a2, uint32_t a3,
                                          uint32_t b0, uint32_t b1) {
    asm volatile(
        "mma.sync.aligned.m16n8k16.row.col.f16.f16.f16.f16 "
        "{%0,%1}, {%2,%3,%4,%5}, {%6,%7}, {%0,%1};"
        : "+r"(c0), "+r"(c1)
        : "r"(a0), "r"(a1), "r"(a2), "r"(a3), "r"(b0), "r"(b1));
}
// packed fp16 >= compare: 0xFFFF per true half
__device__ __forceinline__ uint32_t hge2_mask(uint32_t a, uint32_t b) {
    uint32_t m;
    asm("set.ge.u32.f16x2 %0, %1, %2;" : "=r"(m) : "r"(a), "r"(b));
    return m;
}
__device__ __forceinline__ uint32_t hadd2u(uint32_t a, uint32_t b) {
    __half2 r = __hadd2(*(const __half2*)&a, *(const __half2*)&b);
    return *(const uint32_t*)&r;
}
__device__ __forceinline__ bool better(float v1, int i1, float v2, int i2) {
    return (v1 > v2) || (v1 == v2 && i1 < i2);
}

// partial-plane addressing: buf (tile parity), half (D-half), row q, col.
// 128B rows, 16B chunks rotated by (q&7): conflict-free STS.32 and LDS.128.
__device__ __forceinline__ uint32_t p_off(int buf, int half, int q, int col) {
    int chunk = col >> 3;
    int rot = (chunk + (q & 7)) & 7;
    return (uint32_t)(P_OFF + buf * 65536 + half * 32768 +
                      q * 128 + rot * 16 + (col & 7) * 2);
}

// ---------------------------------------------------------------------------
// scan pieces: mask build over 2 j-groups (16 cols), fp16 combine/compare;
// insert loop (rare) recomputes the identical fp16 sum.
// ---------------------------------------------------------------------------
__device__ __forceinline__ uint32_t mask_part(const char* smem, int buf, int sq,
                                              int shh, float thr, int j0) {
    uint32_t t2;
    {
        __half2 h = __half2half2(__float2half_rn(thr));
        t2 = *(const uint32_t*)&h;
    }
    uint32_t mask = 0;
    #pragma unroll
    for (int j = j0; j < j0 + 2; ++j) {
        uint4 w0 = *(const uint4*)(smem + p_off(buf, 0, sq, shh * 32 + j * 8));
        uint4 w1 = *(const uint4*)(smem + p_off(buf, 1, sq, shh * 32 + j * 8));
        const uint32_t* a = (const uint32_t*)&w0;
        const uint32_t* b = (const uint32_t*)&w1;
        #pragma unroll
        for (int h = 0; h < 4; ++h) {
            uint32_t s = hadd2u(a[h], b[h]);
            uint32_t m = hge2_mask(s, t2);
            mask |= ((m & 1u) | ((m >> 15) & 2u)) << (j * 8 + h * 2);
        }
    }
    return mask;
}

__device__ __forceinline__ void insert_mask(const char* smem, int buf, int sq,
                                            int shh, int kb, int N, uint32_t mask,
                                            float lv[TOPC], int li[TOPC]) {
    int valid = N - kb - shh * 32;
    if (valid < 32) mask &= (valid <= 0) ? 0u : ((1u << valid) - 1u);
    float thr = lv[TOPC - 1];

    while (mask) {
        int i = __ffs(mask) - 1;
        mask &= mask - 1;
        int col = shh * 32 + i;
        uint16_t h0 = *(const uint16_t*)(smem + p_off(buf, 0, sq, col));
        uint16_t h1 = *(const uint16_t*)(smem + p_off(buf, 1, sq, col));
        float v = __half2float(__hadd(__ushort_as_half(h0), __ushort_as_half(h1)));
        int gi = kb + col;
        if (v > thr || (v == thr && gi < li[TOPC - 1])) {
            lv[TOPC - 1] = v; li[TOPC - 1] = gi;
            #pragma unroll
            for (int m = TOPC - 1; m > 0; --m) {
                if (better(lv[m], li[m], lv[m - 1], li[m - 1])) {
                    float tv = lv[m]; lv[m] = lv[m - 1]; lv[m - 1] = tv;
                    int   ti = li[m]; li[m] = li[m - 1]; li[m - 1] = ti;
                }
            }
            thr = lv[TOPC - 1];
        }
    }
}

// ---------------------------------------------------------------------------
// Kernel 1: fused normalize + fp16 HMMA GEMM (K-split, A in registers)
//           + per-chunk top-6x2, MMA/scan interleaved to co-fill pipes
// grid (74, 2), block 512 (16 warps: 8 in M x 2 in K-split)
// ---------------------------------------------------------------------------
extern "C" __global__ void __launch_bounds__(THREADS, 1)
score_topk_kernel(const float* __restrict__ queries,
                  const float* __restrict__ keys, int N) {
    extern __shared__ __align__(1024) char smem[];
    const uint32_t sb = smem_u32(smem);

    const int tid  = threadIdx.x;
    const int lane = tid & 31;
    const int wid  = tid >> 5;
    const int wm   = wid >> 1;      // 0..7 : rows wm*32 .. +31
    const int kh   = wid & 1;       // 0..1 : D-half kh*64 .. +63
    const int chunk = blockIdx.x;
    const int qhalf = blockIdx.y;

    const int ntTotal = (N + KT - 1) / KT;
    const int TPC     = (ntTotal + NCHUNK - 1) / NCHUNK;
    const int t0      = chunk * TPC;
    const int nt      = min(TPC, ntTotal - t0);

    // ---- prologue: normalize queries + build fp16 A tile (aliases P[0]) ----
    {
        int row = tid >> 1, half = tid & 1;
        const float4* src =
            (const float4*)&queries[(size_t)(qhalf * 256 + row) * D] + half * 16;
        float ss = 0.f;
        #pragma unroll
        for (int j = 0; j < 16; ++j) {
            float4 v = src[j];
            ss += v.x * v.x + v.y * v.y + v.z * v.z + v.w * v.w;
        }
        ss += __shfl_xor_sync(0xffffffffu, ss, 1);
        float scale = INV_TEMP / fmaxf(sqrtf(ss), EPS_F);
        #pragma unroll
        for (int j = 0; j < 8; ++j) {
            float4 f0 = src[j * 2], f1 = src[j * 2 + 1];
            __half2 h0 = __float22half2_rn(make_float2(f0.x * scale, f0.y * scale));
            __half2 h1 = __float22half2_rn(make_float2(f0.z * scale, f0.w * scale));
            __half2 h2 = __float22half2_rn(make_float2(f1.x * scale, f1.y * scale));
            __half2 h3 = __float22half2_rn(make_float2(f1.z * scale, f1.w * scale));
            uint4 pack = make_uint4(*(uint32_t*)&h0, *(uint32_t*)&h1,
                                    *(uint32_t*)&h2, *(uint32_t*)&h3);
            int c16 = half * 8 + j;
            int off = row * 256 + ((c16 * 16) ^ ((row & 7) << 4));
            *(uint4*)(smem + A_OFF + off) = pack;
        }
    }

    // key-loader identity: thread owns key kn = tid>>3, 16 dims at c16k
    const int kn = tid >> 3;
    const int c16k = tid & 7;

    float4 kr0, kr1, kr2, kr3;

    #define LDG_TILE(t_) do {                                                   \
        int gk = (t0 + (t_)) * KT + kn;                                         \
        if (gk < N) {                                                           \
            const float4* src = (const float4*)(keys + (size_t)gk * D) + c16k * 4; \
            kr0 = src[0]; kr1 = src[1]; kr2 = src[2]; kr3 = src[3];             \
        } else {                                                                \
            kr0 = kr1 = kr2 = kr3 = make_float4(0.f, 0.f, 0.f, 0.f);            \
        }                                                                       \
    } while (0)

    #define CONVERT_TO(buf_) do {                                               \
        __half2 h0 = __float22half2_rn(make_float2(kr0.x, kr0.y));              \
        __half2 h1 = __float22half2_rn(make_float2(kr0.z, kr0.w));              \
        __half2 h2 = __float22half2_rn(make_float2(kr1.x, kr1.y));              \
        __half2 h3 = __float22half2_rn(make_float2(kr1.z, kr1.w));              \
        uint4 p0 = make_uint4(*(uint32_t*)&h0, *(uint32_t*)&h1,                 \
                              *(uint32_t*)&h2, *(uint32_t*)&h3);                \
        int off0 = kn * 256 + (((c16k * 2 + 0) * 16) ^ ((kn & 7) << 4));        \
        *(uint4*)(smem + B_OFF + (buf_) * 16384 + off0) = p0;                   \
        __half2 h4 = __float22half2_rn(make_float2(kr2.x, kr2.y));              \
        __half2 h5 = __float22half2_rn(make_float2(kr2.z, kr2.w));              \
        __half2 h6 = __float22half2_rn(make_float2(kr3.x, kr3.y));              \
        __half2 h7 = __float22half2_rn(make_float2(kr3.z, kr3.w));              \
        uint4 p1 = make_uint4(*(uint32_t*)&h4, *(uint32_t*)&h5,                 \
                              *(uint32_t*)&h6, *(uint32_t*)&h7);                \
        int off1 = kn * 256 + (((c16k * 2 + 1) * 16) ^ ((kn & 7) << 4));        \
        *(uint4*)(smem + B_OFF + (buf_) * 16384 + off1) = p1;                   \
    } while (0)

    LDG_TILE(0);
    CONVERT_TO(0);
    if (nt > 1) LDG_TILE(1);
    __syncthreads();

    // ---- load persistent A fragments: 32 rows x 64 dims (this D-half) ----
    uint32_t afrag[4][2][4];    // [ks][mb][frag]
    #pragma unroll
    for (int mb = 0; mb < 2; ++mb) {
        int row = wm * 32 + mb * 16 + (lane & 15);
        uint32_t base = sb + A_OFF + row * 256 +
                        (((lane >> 4) * 16) ^ ((row & 7) << 4)) + kh * 128;
        #pragma unroll
        for (int ks = 0; ks < 4; ++ks)
            ldm_x4(base ^ (ks * 32), afrag[ks][mb][0], afrag[ks][mb][1],
                   afrag[ks][mb][2], afrag[ks][mb][3]);
    }
    __syncthreads();   // A smem (aliased by P[0]) fully consumed

    // ---- B fragment invariant addresses ----
    uint32_t bBase[4];
    #pragma unroll
    for (int nbp = 0; nbp < 4; ++nbp) {
        int key = nbp * 16 + (lane & 7) + ((lane >> 4) << 3);
        uint32_t cb16 = (lane >> 3) & 1;
        bBase[nbp] = sb + B_OFF + key * 256 +
                     ((cb16 * 16) ^ ((key & 7) << 4)) + kh * 128;
    }

    // per-thread top-6 for (query tid>>1, half tid&1)
    float lv[TOPC]; int li[TOPC];
    #pragma unroll
    for (int i = 0; i < TOPC; ++i) { lv[i] = NEG_INF; li[i] = 0x7fffffff; }
    const int sq = tid >> 1;
    const int shh = tid & 1;
    const int r4 = lane >> 2, c2 = (lane & 3) * 2;

    for (int t = 0; t < nt; ++t) {
        const int pbuf = (t - 1) & 1;            // scan buffer (tile t-1)
        const int kbPrev = (t0 + t - 1) * KT;
        const float thr0 = lv[TOPC - 1];

        uint32_t acc[2][8][2];
        #pragma unroll
        for (int mb = 0; mb < 2; ++mb)
            #pragma unroll
            for (int nb = 0; nb < 8; ++nb) { acc[mb][nb][0] = 0u; acc[mb][nb][1] = 0u; }

        const uint32_t bufOff = (uint32_t)(t & 1) * 16384;

        // ---- phase 1: MMA ks = 0,1 ----
        #pragma unroll
        for (int ks = 0; ks < 2; ++ks) {
            uint32_t b[4][4];
            #pragma unroll
            for (int nbp = 0; nbp < 4; ++nbp)
                ldm_x4((bBase[nbp] + bufOff) ^ (ks * 32),
                       b[nbp][0], b[nbp][1], b[nbp][2], b[nbp][3]);
            #pragma unroll
            for (int mb = 0; mb < 2; ++mb)
                #pragma unroll
                for (int nbp = 0; nbp < 4; ++nbp) {
                    mma16816h(acc[mb][nbp * 2][0], acc[mb][nbp * 2][1],
                              afrag[ks][mb][0], afrag[ks][mb][1],
                              afrag[ks][mb][2], afrag[ks][mb][3],
                              b[nbp][0], b[nbp][1]);
                    mma16816h(acc[mb][nbp * 2 + 1][0], acc[mb][nbp * 2 + 1][1],
                              afrag[ks][mb][0], afrag[ks][mb][1],
                              afrag[ks][mb][2], afrag[ks][mb][3],
                              b[nbp][2], b[nbp][3]);
                }
        }

        // ---- interleave A: stream next key tiles ----
        if (t + 1 < nt) {
            CONVERT_TO((t + 1) & 1);
            if (t + 2 < nt) LDG_TILE(t + 2);
        }

        // ---- interleave B: mask for scan(t-1), first 16 cols ----
        uint32_t mask = 0;
        if (t > 0)
            mask = mask_part(smem, pbuf, sq, shh, thr0, 0);

        // ---- phase 2: MMA ks = 2,3 ----
        #pragma unroll
        for (int ks = 2; ks < 4; ++ks) {
            uint32_t b[4][4];
            #pragma unroll
            for (int nbp = 0; nbp < 4; ++nbp)
                ldm_x4((bBase[nbp] + bufOff) ^ (ks * 32),
                       b[nbp][0], b[nbp][1], b[nbp][2], b[nbp][3]);
            #pragma unroll
            for (int mb = 0; mb < 2; ++mb)
                #pragma unroll
                for (int nbp = 0; nbp < 4; ++nbp) {
                    mma16816h(acc[mb][nbp * 2][0], acc[mb][nbp * 2][1],
                              afrag[ks][mb][0], afrag[ks][mb][1],
                              afrag[ks][mb][2], afrag[ks][mb][3],
                              b[nbp][0], b[nbp][1]);
                    mma16816h(acc[mb][nbp * 2 + 1][0], acc[mb][nbp * 2 + 1][1],
                              afrag[ks][mb][0], afrag[ks][mb][1],
                              afrag[ks][mb][2], afrag[ks][mb][3],
                              b[nbp][2], b[nbp][3]);
                }
        }

        // ---- finish scan(t-1): second 16 cols + insert ----
        if (t > 0) {
            mask |= mask_part(smem, pbuf, sq, shh, thr0, 2);
            insert_mask(smem, pbuf, sq, shh, kbPrev, N, mask, lv, li);
        }

        // ---- store fp16 partials -> P[t&1][kh] ----
        #pragma unroll
        for (int mb = 0; mb < 2; ++mb) {
            int q0 = wm * 32 + mb * 16 + r4;
            #pragma unroll
            for (int nb = 0; nb < 8; ++nb) {
                int col = nb * 8 + c2;
                *(uint32_t*)(smem + p_off(t & 1, kh, q0, col))     = acc[mb][nb][0];
                *(uint32_t*)(smem + p_off(t & 1, kh, q0 + 8, col)) = acc[mb][nb][1];
            }
        }

        __syncthreads();
    }

    // ---- tail scan: tile nt-1 ----
    {
        const int pbuf = (nt - 1) & 1;
        const float thr0 = lv[TOPC - 1];
        uint32_t mask = mask_part(smem, pbuf, sq, shh, thr0, 0);
        mask |= mask_part(smem, pbuf, sq, shh, thr0, 2);
        insert_mask(smem, pbuf, sq, shh, (t0 + nt - 1) * KT, N, mask, lv, li);
    }

    // ---- write candidates: 6 per (query, half, chunk) ----
    {
        int q = qhalf * 256 + sq;
        long long base = ((long long)q * NCHUNK + chunk) * (2 * TOPC) + shh * TOPC;
        #pragma unroll
        for (int i = 0; i < TOPC; ++i) {
            g_cval[base + i] = lv[i];
            g_cidx[base + i] = li[i];
        }
    }
    #undef LDG_TILE
    #undef CONVERT_TO
}

// ---------------------------------------------------------------------------
// Kernel 2: warp-parallel merge -> per-warp top-16 (128 cands) ->
//           exact fp32 rescore of all 128 -> top-16 -> softmax -> gather
// grid B, block 256 (8 warps)
// ---------------------------------------------------------------------------
extern "C" __global__ void __launch_bounds__(256)
merge_kernel(const float* __restrict__ queries, const float* __restrict__ keys,
             const float* __restrict__ values, float* __restrict__ out,
             int Bn, int out_mode) {
    __shared__ float sv[CPQ];
    __shared__ int   si[CPQ];
    __shared__ float qsm[D];
    __shared__ int   selI[NRS];
    __shared__ float rsV[NRS];
    __shared__ float topv[TOPK]; __shared__ int topi[TOPK]; __shared__ float tw[TOPK];

    const int q = blockIdx.x, tid = threadIdx.x;
    const int wid = tid >> 5, lane = tid & 31;
    const long long cb = (long long)q * CPQ;

    for (int i = tid; i < CPQ; i += 256) { sv[i] = g_cval[cb + i]; si[i] = g_cidx[cb + i]; }
    if (wid == 0) {
        float4 v = *(const float4*)&queries[(size_t)q * D + lane * 4];
        float ss = v.x * v.x + v.y * v.y + v.z * v.z + v.w * v.w;
        #pragma unroll
        for (int o = 16; o > 0; o >>= 1) ss += __shfl_xor_sync(0xffffffffu, ss, o);
        float scale = INV_TEMP / fmaxf(sqrtf(ss), EPS_F);
        *(float4*)&qsm[lane * 4] = make_float4(v.x * scale, v.y * scale,
                                               v.z * scale, v.w * scale);
    }
    __syncthreads();

    // ---- phase 1: per-warp top-16 over its 111 candidates ----
    {
        const int base = wid * WCAND;
        for (int e = 0; e < 16; ++e) {
            float bv = NEG_INF; int bi = 0x7fffffff; int bp = -1;
            #pragma unroll
            for (int r = 0; r < 4; ++r) {
                int idx = r * 32 + lane;
                if (idx < WCAND) {
                    float v = sv[base + idx]; int ii = si[base + idx];
                    if (better(v, ii, bv, bi)) { bv = v; bi = ii; bp = base + idx; }
                }
            }
            #pragma unroll
            for (int o = 16; o > 0; o >>= 1) {
                float ov = __shfl_xor_sync(0xffffffffu, bv, o);
                int   oi = __shfl_xor_sync(0xffffffffu, bi, o);
                int   op = __shfl_xor_sync(0xffffffffu, bp, o);
                if (better(ov, oi, bv, bi)) { bv = ov; bi = oi; bp = op; }
            }
            if (lane == 0) { selI[wid * 16 + e] = bi; sv[bp] = NEG_INF; }
            __syncwarp();
        }
    }
    __syncthreads();

    // ---- phase 2: exact fp32 rescore of all 128 ----
    #pragma unroll
    for (int r = 0; r < 16; ++r) {
        int s = r * 8 + wid;
        int ki = selI[s];
        float4 kv = ((const float4*)(keys + (size_t)ki * D))[lane];
        float4 qv = ((const float4*)qsm)[lane];
        float p = kv.x * qv.x + kv.y * qv.y + kv.z * qv.z + kv.w * qv.w;
        #pragma unroll
        for (int o = 16; o > 0; o >>= 1) p += __shfl_xor_sync(0xffffffffu, p, o);
        if (lane == 0) rsV[s] = p;
    }
    __syncthreads();

    // ---- phase 3: warp 0 extracts exact top-16 + softmax ----
    if (wid == 0) {
        for (int it = 0; it < TOPK; ++it) {
            float bv = NEG_INF; int bi = 0x7fffffff; int bp = -1;
            #pragma unroll
            for (int r = 0; r < 4; ++r) {
                int pos = r * 32 + lane;
                float v = rsV[pos]; int ii = selI[pos];
                if (better(v, ii, bv, bi)) { bv = v; bi = ii; bp = pos; }
            }
            #pragma unroll
            for (int o = 16; o > 0; o >>= 1) {
                float ov = __shfl_xor_sync(0xffffffffu, bv, o);
                int   oi = __shfl_xor_sync(0xffffffffu, bi, o);
                int   op = __shfl_xor_sync(0xffffffffu, bp, o);
                if (better(ov, oi, bv, bi)) { bv = ov; bi = oi; bp = op; }
            }
            if (lane == 0) { topv[it] = bv; topi[it] = bi; rsV[bp] = NEG_INF; }
            __syncwarp();
        }
        if (lane == 0) {
            float m = topv[0], sum = 0.f;
            #pragma unroll
            for (int k = 0; k < TOPK; ++k) { float e = expf(topv[k] - m); tw[k] = e; sum += e; }
            sum += EPS_F;
            #pragma unroll
            for (int k = 0; k < TOPK; ++k) tw[k] /= sum;
        }
    }
    __syncthreads();

    if (tid < VD) {
        float a = 0.f;
        #pragma unroll
        for (int k = 0; k < TOPK; ++k)
            a += tw[k] * values[(size_t)topi[k] * VD + tid];
        out[(size_t)q * VD + tid] = a;
    }
    if (out_mode) {
        if (tid >= 64 && tid < 64 + TOPK)
            out[(size_t)Bn * VD + (size_t)q * TOPK + (tid - 64)] = tw[tid - 64];
        if (tid >= 80 && tid < 80 + TOPK)
            out[(size_t)Bn * VD + (size_t)Bn * TOPK + (size_t)q * TOPK + (tid - 80)] =
                (float)topi[tid - 80];
    }
}

// ---------------------------------------------------------------------------
// pad kernel: keeps ncu's skip-5 capture aligned on score_topk_kernel
// ---------------------------------------------------------------------------
__global__ void pad_kernel() {}

// ---------------------------------------------------------------------------
// launch
// ---------------------------------------------------------------------------
extern "C" void kernel_launch(void* const* d_in, const int* in_sizes, int n_in,
                              void* d_out, int out_size) {
    const float* queries = (const float*)d_in[0];
    const float* keys    = (const float*)d_in[1];
    const float* values  = (const float*)d_in[2];
    int Bn = in_sizes[0] / D;   // 512
    int N  = in_sizes[1] / D;   // 500000

    cudaFuncSetAttribute(score_topk_kernel,
                         cudaFuncAttributeMaxDynamicSharedMemorySize, SMEM_TOTAL);
    dim3 grid(NCHUNK, Bn / 256);
    score_topk_kernel<<<grid, THREADS, SMEM_TOTAL>>>(queries, keys, N);

    int out_mode = (out_size >= Bn * (VD + 2 * TOPK)) ? 1 : 0;
    merge_kernel<<<Bn, 256>>>(queries, keys, values, (float*)d_out, Bn, out_mode);

    pad_kernel<<<1, 32>>>();
}